// round 2
// baseline (speedup 1.0000x reference)
#include <cuda_runtime.h>
#include <math.h>

// Fixed problem shapes (from reference): N=50000 atoms, E=1.6M edges, D=64, d_out=128
#define MAXN 50000
#define MAXE 1600000

// Scratch (device globals: allocation-free rule)
__device__ float  g_P[(size_t)MAXN * 256];     // [N][256]: cols 0..127 = atom@W1+b, 128..255 = atom@W2
__device__ float  g_z[(size_t)MAXE * 128];     // pre-BN edge activations
__device__ float  g_upd[(size_t)MAXN * 64];    // scatter-add accumulator
__device__ double g_s1[256];                   // [0..127]=sum, [128..255]=sumsq  (BN1)
__device__ double g_s2[128];                   // [0..63]=sum,  [64..127]=sumsq   (BN2)
__device__ float  g_scale1[128], g_shift1[128];
__device__ float  g_scale2[64],  g_shift2[64];

__device__ __forceinline__ float softplusf(float x) {
    return fmaxf(x, 0.0f) + log1pf(expf(-fabsf(x)));
}
__device__ __forceinline__ float sigmoidf(float x) {
    return 1.0f / (1.0f + expf(-x));
}

// ---------------------------------------------------------------- K0: zero scratch
__global__ void k_zero(int N) {
    int i = blockIdx.x * blockDim.x + threadIdx.x;
    int total = N * 64;
    int stride = gridDim.x * blockDim.x;
    for (; i < total; i += stride) {
        g_upd[i] = 0.0f;
        if (i < 256) g_s1[i] = 0.0;
        if (i < 128) g_s2[i] = 0.0;
    }
}

// ---------------------------------------------------------------- K1: P1/P2 precompute
// grid: (2, ceil(N/128)); half 0 -> cols [0,128) uses W rows [0,64) and +b
//                          half 1 -> cols [128,256) uses W rows [64,128)
__global__ void k_precompute(const float* __restrict__ atom,
                             const float* __restrict__ W,
                             const float* __restrict__ b, int N) {
    __shared__ float As[32 * 128];   // k-chunk x 128 atoms (transposed)
    __shared__ float Bs[64 * 128];   // k x 128 cols
    const int half = blockIdx.x;
    const int ab = blockIdx.y * 128;
    const int tid = threadIdx.x;

    for (int i = tid; i < 64 * 128; i += 256)
        Bs[i] = W[(half * 64 + (i >> 7)) * 128 + (i & 127)];

    const int ty = tid >> 4, tx = tid & 15;
    const int r0 = ty * 8, c0 = tx * 8;
    float acc[64];
#pragma unroll
    for (int i = 0; i < 64; i++) acc[i] = 0.0f;

    for (int kk = 0; kk < 64; kk += 32) {
        for (int li = tid; li < 1024; li += 256) {
            int row = li >> 3, kq = (li & 7) * 4;
            float4 v = make_float4(0.f, 0.f, 0.f, 0.f);
            if (ab + row < N)
                v = *(const float4*)&atom[(size_t)(ab + row) * 64 + kk + kq];
            As[(kq + 0) * 128 + row] = v.x;
            As[(kq + 1) * 128 + row] = v.y;
            As[(kq + 2) * 128 + row] = v.z;
            As[(kq + 3) * 128 + row] = v.w;
        }
        __syncthreads();
#pragma unroll 8
        for (int k = 0; k < 32; ++k) {
            const float* Ak = &As[k * 128];
            const float* Bk = &Bs[(kk + k) * 128];
            float4 a0 = *(const float4*)(Ak + r0);
            float4 a1 = *(const float4*)(Ak + r0 + 4);
            float4 b0 = *(const float4*)(Bk + c0);
            float4 b1 = *(const float4*)(Bk + c0 + 4);
            float av[8] = {a0.x, a0.y, a0.z, a0.w, a1.x, a1.y, a1.z, a1.w};
            float bv[8] = {b0.x, b0.y, b0.z, b0.w, b1.x, b1.y, b1.z, b1.w};
#pragma unroll
            for (int i = 0; i < 8; i++)
#pragma unroll
                for (int j = 0; j < 8; j++)
                    acc[i * 8 + j] = fmaf(av[i], bv[j], acc[i * 8 + j]);
        }
        __syncthreads();
    }

    float bias[8];
#pragma unroll
    for (int j = 0; j < 8; j++) bias[j] = (half == 0) ? b[c0 + j] : 0.0f;

#pragma unroll
    for (int i = 0; i < 8; i++) {
        int row = ab + r0 + i;
        if (row < N) {
            float* dst = &g_P[(size_t)row * 256 + half * 128 + c0];
            float4 o0 = make_float4(acc[i*8+0]+bias[0], acc[i*8+1]+bias[1],
                                    acc[i*8+2]+bias[2], acc[i*8+3]+bias[3]);
            float4 o1 = make_float4(acc[i*8+4]+bias[4], acc[i*8+5]+bias[5],
                                    acc[i*8+6]+bias[6], acc[i*8+7]+bias[7]);
            *(float4*)(dst)     = o0;
            *(float4*)(dst + 4) = o1;
        }
    }
}

// ---------------------------------------------------------------- K2: edge GEMM + gather + stats
// z[e] = nbr[e] @ W3 + P1[src[e]] + P2[dst[e]]   (bias folded into P1)
// also accumulates per-column sum / sumsq into g_s1
__global__ void k_edge_gemm(const float* __restrict__ nbr,
                            const float* __restrict__ W,
                            const int* __restrict__ esrc,
                            const int* __restrict__ edst, int E) {
    __shared__ float As[32 * 128];   // k-chunk x 128 edges (transposed)
    __shared__ float Bs[64 * 128];   // W3: k x 128
    const int eb = blockIdx.x * 128;
    const int tid = threadIdx.x;

    for (int i = tid; i < 64 * 128; i += 256)
        Bs[i] = W[(128 + (i >> 7)) * 128 + (i & 127)];

    const int ty = tid >> 4, tx = tid & 15;
    const int r0 = ty * 8, c0 = tx * 8;
    float acc[64];
#pragma unroll
    for (int i = 0; i < 64; i++) acc[i] = 0.0f;

    for (int kk = 0; kk < 64; kk += 32) {
        for (int li = tid; li < 1024; li += 256) {
            int row = li >> 3, kq = (li & 7) * 4;
            float4 v = make_float4(0.f, 0.f, 0.f, 0.f);
            if (eb + row < E)
                v = *(const float4*)&nbr[(size_t)(eb + row) * 64 + kk + kq];
            As[(kq + 0) * 128 + row] = v.x;
            As[(kq + 1) * 128 + row] = v.y;
            As[(kq + 2) * 128 + row] = v.z;
            As[(kq + 3) * 128 + row] = v.w;
        }
        __syncthreads();
#pragma unroll 8
        for (int k = 0; k < 32; ++k) {
            const float* Ak = &As[k * 128];
            const float* Bk = &Bs[(kk + k) * 128];
            float4 a0 = *(const float4*)(Ak + r0);
            float4 a1 = *(const float4*)(Ak + r0 + 4);
            float4 b0 = *(const float4*)(Bk + c0);
            float4 b1 = *(const float4*)(Bk + c0 + 4);
            float av[8] = {a0.x, a0.y, a0.z, a0.w, a1.x, a1.y, a1.z, a1.w};
            float bv[8] = {b0.x, b0.y, b0.z, b0.w, b1.x, b1.y, b1.z, b1.w};
#pragma unroll
            for (int i = 0; i < 8; i++)
#pragma unroll
                for (int j = 0; j < 8; j++)
                    acc[i * 8 + j] = fmaf(av[i], bv[j], acc[i * 8 + j]);
        }
        __syncthreads();
    }

    // epilogue: gather P1[src], P2[dst], store z, local column stats
    float colsum[8], colsq[8];
#pragma unroll
    for (int j = 0; j < 8; j++) { colsum[j] = 0.0f; colsq[j] = 0.0f; }

#pragma unroll
    for (int i = 0; i < 8; i++) {
        int e = eb + r0 + i;
        if (e < E) {
            int s = esrc[e], d = edst[e];
            float4 p0 = *(const float4*)&g_P[(size_t)s * 256 + c0];
            float4 p1 = *(const float4*)&g_P[(size_t)s * 256 + c0 + 4];
            float4 q0 = *(const float4*)&g_P[(size_t)d * 256 + 128 + c0];
            float4 q1 = *(const float4*)&g_P[(size_t)d * 256 + 128 + c0 + 4];
            float v[8];
            v[0] = acc[i*8+0] + p0.x + q0.x;  v[1] = acc[i*8+1] + p0.y + q0.y;
            v[2] = acc[i*8+2] + p0.z + q0.z;  v[3] = acc[i*8+3] + p0.w + q0.w;
            v[4] = acc[i*8+4] + p1.x + q1.x;  v[5] = acc[i*8+5] + p1.y + q1.y;
            v[6] = acc[i*8+6] + p1.z + q1.z;  v[7] = acc[i*8+7] + p1.w + q1.w;
            float* zr = &g_z[(size_t)e * 128 + c0];
            *(float4*)(zr)     = make_float4(v[0], v[1], v[2], v[3]);
            *(float4*)(zr + 4) = make_float4(v[4], v[5], v[6], v[7]);
#pragma unroll
            for (int j = 0; j < 8; j++) { colsum[j] += v[j]; colsq[j] += v[j] * v[j]; }
        }
    }

    // reduce stats across the 16 row-groups (reuse As: 16KB needed, 16KB available)
    float* psum = As;            // [16][128]
    float* psq  = As + 2048;     // [16][128]
#pragma unroll
    for (int j = 0; j < 8; j++) {
        psum[ty * 128 + c0 + j] = colsum[j];
        psq [ty * 128 + c0 + j] = colsq[j];
    }
    __syncthreads();
    int col = tid & 127;
    int which = tid >> 7;   // 0 -> sum, 1 -> sumsq
    const float* srcp = which ? psq : psum;
    float v = 0.0f;
#pragma unroll
    for (int p = 0; p < 16; p++) v += srcp[p * 128 + col];
    atomicAdd(&g_s1[which * 128 + col], (double)v);
}

// ---------------------------------------------------------------- K3: BN1 finalize
__global__ void k_bn1(const float* __restrict__ g1, const float* __restrict__ b1, int E) {
    int j = threadIdx.x;  // 128
    double mean = g_s1[j] / (double)E;
    double var  = g_s1[128 + j] / (double)E - mean * mean;
    float istd = (float)rsqrt(var + 1e-5);
    float sc = g1[j] * istd;
    g_scale1[j] = sc;
    g_shift1[j] = b1[j] - (float)mean * sc;
}

// ---------------------------------------------------------------- K4: BN1 + gated message + scatter-add
// one warp per edge; lanes cover the 64 message columns (j = lane, lane+32)
__global__ void k_msg(const int* __restrict__ edst, int E) {
    int gw = (int)((blockIdx.x * (size_t)blockDim.x + threadIdx.x) >> 5);
    int lane = threadIdx.x & 31;
    if (gw >= E) return;
    const float* zr = g_z + (size_t)gw * 128;
    float f0 = zr[lane]      * g_scale1[lane]      + g_shift1[lane];
    float f1 = zr[32 + lane] * g_scale1[32 + lane] + g_shift1[32 + lane];
    float c0 = zr[64 + lane] * g_scale1[64 + lane] + g_shift1[64 + lane];
    float c1 = zr[96 + lane] * g_scale1[96 + lane] + g_shift1[96 + lane];
    float m0 = sigmoidf(f0) * softplusf(c0);
    float m1 = sigmoidf(f1) * softplusf(c1);
    int d = edst[gw];
    atomicAdd(&g_upd[(size_t)d * 64 + lane],      m0);
    atomicAdd(&g_upd[(size_t)d * 64 + 32 + lane], m1);
}

// ---------------------------------------------------------------- K5: BN2 stats
__global__ void k_stats2(int N) {
    __shared__ double ssum[64], ssq[64];
    int tid = threadIdx.x;  // 256
    if (tid < 64) { ssum[tid] = 0.0; ssq[tid] = 0.0; }
    __syncthreads();
    int col = tid & 63;
    int r = blockIdx.x * 4 + (tid >> 6);
    float s = 0.0f, q = 0.0f;
    for (; r < N; r += gridDim.x * 4) {
        float v = g_upd[(size_t)r * 64 + col];
        s += v; q += v * v;
    }
    atomicAdd(&ssum[col], (double)s);
    atomicAdd(&ssq[col], (double)q);
    __syncthreads();
    if (tid < 64) {
        atomicAdd(&g_s2[tid], ssum[tid]);
        atomicAdd(&g_s2[64 + tid], ssq[tid]);
    }
}

// ---------------------------------------------------------------- K6: BN2 finalize
__global__ void k_bn2(const float* __restrict__ g2, const float* __restrict__ b2, int N) {
    int j = threadIdx.x;  // 64
    double mean = g_s2[j] / (double)N;
    double var  = g_s2[64 + j] / (double)N - mean * mean;
    float istd = (float)rsqrt(var + 1e-5);
    float sc = g2[j] * istd;
    g_scale2[j] = sc;
    g_shift2[j] = b2[j] - (float)mean * sc;
}

// ---------------------------------------------------------------- K7: output
__global__ void k_out(const float* __restrict__ atom, float* __restrict__ out, int N) {
    int i = blockIdx.x * blockDim.x + threadIdx.x;
    int total = N * 64;
    if (i >= total) return;
    int col = i & 63;
    float u = g_upd[i] * g_scale2[col] + g_shift2[col];
    out[i] = softplusf(atom[i] + u);
}

// ----------------------------------------------------------------
extern "C" void kernel_launch(void* const* d_in, const int* in_sizes, int n_in,
                              void* d_out, int out_size) {
    const float* atom = (const float*)d_in[0];
    const float* nbr  = (const float*)d_in[1];
    const int*   esrc = (const int*)d_in[2];
    const int*   edst = (const int*)d_in[3];
    const float* W    = (const float*)d_in[4];
    const float* b    = (const float*)d_in[5];
    const float* bn1g = (const float*)d_in[6];
    const float* bn1b = (const float*)d_in[7];
    const float* bn2g = (const float*)d_in[8];
    const float* bn2b = (const float*)d_in[9];
    float* out = (float*)d_out;

    int N = in_sizes[0] / 64;
    int E = in_sizes[2];

    k_zero<<<2048, 256>>>(N);
    dim3 gP(2, (N + 127) / 128);
    k_precompute<<<gP, 256>>>(atom, W, b, N);
    k_edge_gemm<<<(E + 127) / 128, 256>>>(nbr, W, esrc, edst, E);
    k_bn1<<<1, 128>>>(bn1g, bn1b, E);
    {
        long long threads = (long long)E * 32;
        int grid = (int)((threads + 255) / 256);
        k_msg<<<grid, 256>>>(edst, E);
    }
    k_stats2<<<128, 256>>>(N);
    k_bn2<<<1, 64>>>(bn2g, bn2b, N);
    k_out<<<(N * 64 + 255) / 256, 256>>>(atom, out, N);
}

// round 4
// speedup vs baseline: 1.2570x; 1.2570x over previous
#include <cuda_runtime.h>
#include <cuda_bf16.h>
#include <math.h>
#include <stdint.h>

// Shapes: N=50000 atoms (D=64), E=1.6M edges, W[192][128]
#define MAXN 50000
#define MAXE 1600000
#define NREP 128

// ---------------- device scratch (allocation-free rule) ----------------
__device__ float  g_P[(size_t)MAXN * 256];     // [N][256]: 0..127 = atom@W1+b, 128..255 = atom@W2
__device__ float  g_z[(size_t)MAXE * 128];     // pre-BN edge activations
__device__ float  g_upd[(size_t)MAXN * 64];    // scatter-add accumulator
__device__ float  g_sumf[NREP][128];           // replicated BN1 sum (float, fire-and-forget reds)
__device__ float  g_sqf[NREP][128];            // replicated BN1 sumsq
__device__ double g_s2[128];                   // BN2: [0..63 sum, 64..127 sumsq]
__device__ float  g_scale1[128], g_shift1[128];
__device__ float  g_scale2[64],  g_shift2[64];
__device__ uint2  g_wfh[2048];                 // W3 bf16-hi mma B fragments [kk][nt][lane]
__device__ uint2  g_wfl[2048];                 // W3 bf16-lo residual fragments

__device__ __forceinline__ float softplusf(float x) {
    return fmaxf(x, 0.0f) + log1pf(expf(-fabsf(x)));
}
__device__ __forceinline__ float sigmoidf(float x) {
    return 1.0f / (1.0f + expf(-x));
}
__device__ __forceinline__ uint32_t packbf(float a, float b) {
    __nv_bfloat162 t = __halves2bfloat162(__float2bfloat16(a), __float2bfloat16(b));
    return *reinterpret_cast<uint32_t*>(&t);
}
__device__ __forceinline__ uint32_t packlo(float a, float ha, float b, float hb) {
    // residuals a - bf16(a)
    return packbf(a - ha, b - hb);
}

#define MMA_BF16(c, a, b0, b1)                                              \
    asm volatile(                                                           \
        "mma.sync.aligned.m16n8k16.row.col.f32.bf16.bf16.f32 "              \
        "{%0,%1,%2,%3}, {%4,%5,%6,%7}, {%8,%9}, {%0,%1,%2,%3};"             \
        : "+f"((c)[0]), "+f"((c)[1]), "+f"((c)[2]), "+f"((c)[3])            \
        : "r"((a)[0]), "r"((a)[1]), "r"((a)[2]), "r"((a)[3]),               \
          "r"(b0), "r"(b1))

// ---------------------------------------------------------------- K0: zero scratch
__global__ void k_zero(int N) {
    int t = blockIdx.x * blockDim.x + threadIdx.x;
    if (t < NREP * 128) { ((float*)g_sumf)[t] = 0.0f; ((float*)g_sqf)[t] = 0.0f; }
    if (t < 128) g_s2[t] = 0.0;
    int total = N * 64;
    int stride = gridDim.x * blockDim.x;
    for (int i = t; i < total; i += stride) g_upd[i] = 0.0f;
}

// ---------------------------------------------------------------- K0b: W3 -> mma B fragments (hi/lo)
// fragment index: [kk 0..3][nt 0..15][lane 0..31], g=lane>>2, tig=lane&3
// B tile (kstep kk, ntile nt): reg0 = {Wb[k0][n], Wb[k0+1][n]}, reg1 = {Wb[k0+8][n], Wb[k0+9][n]}
// with k0 = 16*kk + 2*tig, n = 8*nt + g, Wb[k][n] = W[(128+k)*128 + n]
__global__ void k_prepW(const float* __restrict__ W) {
    int tid = blockIdx.x * blockDim.x + threadIdx.x;
    if (tid >= 2048) return;
    int lane = tid & 31, nt = (tid >> 5) & 15, kk = tid >> 9;
    int g = lane >> 2, tig = lane & 3;
    int n = 8 * nt + g;
    int k0 = 16 * kk + 2 * tig;
    float w0 = W[(128 + k0) * 128 + n];
    float w1 = W[(128 + k0 + 1) * 128 + n];
    float w8 = W[(128 + k0 + 8) * 128 + n];
    float w9 = W[(128 + k0 + 9) * 128 + n];
    uint32_t h0 = packbf(w0, w1);
    uint32_t h1 = packbf(w8, w9);
    __nv_bfloat162 hh0 = *reinterpret_cast<__nv_bfloat162*>(&h0);
    __nv_bfloat162 hh1 = *reinterpret_cast<__nv_bfloat162*>(&h1);
    uint32_t l0 = packbf(w0 - __bfloat162float(hh0.x), w1 - __bfloat162float(hh0.y));
    uint32_t l1 = packbf(w8 - __bfloat162float(hh1.x), w9 - __bfloat162float(hh1.y));
    g_wfh[tid] = make_uint2(h0, h1);
    g_wfl[tid] = make_uint2(l0, l1);
}

// ---------------------------------------------------------------- K1: P1/P2 precompute (FFMA; small)
__global__ void k_precompute(const float* __restrict__ atom,
                             const float* __restrict__ W,
                             const float* __restrict__ b, int N) {
    __shared__ float As[32 * 128];
    __shared__ float Bs[64 * 128];
    const int half = blockIdx.x;
    const int ab = blockIdx.y * 128;
    const int tid = threadIdx.x;

    for (int i = tid; i < 64 * 128; i += 256)
        Bs[i] = W[(half * 64 + (i >> 7)) * 128 + (i & 127)];

    const int ty = tid >> 4, tx = tid & 15;
    const int r0 = ty * 8, c0 = tx * 8;
    float acc[64];
#pragma unroll
    for (int i = 0; i < 64; i++) acc[i] = 0.0f;

    for (int kk = 0; kk < 64; kk += 32) {
        for (int li = tid; li < 1024; li += 256) {
            int row = li >> 3, kq = (li & 7) * 4;
            float4 v = make_float4(0.f, 0.f, 0.f, 0.f);
            if (ab + row < N)
                v = *(const float4*)&atom[(size_t)(ab + row) * 64 + kk + kq];
            As[(kq + 0) * 128 + row] = v.x;
            As[(kq + 1) * 128 + row] = v.y;
            As[(kq + 2) * 128 + row] = v.z;
            As[(kq + 3) * 128 + row] = v.w;
        }
        __syncthreads();
#pragma unroll 8
        for (int k = 0; k < 32; ++k) {
            const float* Ak = &As[k * 128];
            const float* Bk = &Bs[(kk + k) * 128];
            float4 a0 = *(const float4*)(Ak + r0);
            float4 a1 = *(const float4*)(Ak + r0 + 4);
            float4 b0 = *(const float4*)(Bk + c0);
            float4 b1 = *(const float4*)(Bk + c0 + 4);
            float av[8] = {a0.x, a0.y, a0.z, a0.w, a1.x, a1.y, a1.z, a1.w};
            float bv[8] = {b0.x, b0.y, b0.z, b0.w, b1.x, b1.y, b1.z, b1.w};
#pragma unroll
            for (int i = 0; i < 8; i++)
#pragma unroll
                for (int j = 0; j < 8; j++)
                    acc[i * 8 + j] = fmaf(av[i], bv[j], acc[i * 8 + j]);
        }
        __syncthreads();
    }

    float bias[8];
#pragma unroll
    for (int j = 0; j < 8; j++) bias[j] = (half == 0) ? b[c0 + j] : 0.0f;

#pragma unroll
    for (int i = 0; i < 8; i++) {
        int row = ab + r0 + i;
        if (row < N) {
            float* dst = &g_P[(size_t)row * 256 + half * 128 + c0];
            *(float4*)(dst)     = make_float4(acc[i*8+0]+bias[0], acc[i*8+1]+bias[1],
                                              acc[i*8+2]+bias[2], acc[i*8+3]+bias[3]);
            *(float4*)(dst + 4) = make_float4(acc[i*8+4]+bias[4], acc[i*8+5]+bias[5],
                                              acc[i*8+6]+bias[6], acc[i*8+7]+bias[7]);
        }
    }
}

// ---------------------------------------------------------------- K2: HMMA edge GEMM + gather + stats
// z[e] = nbr[e] @ W3 + P1[src[e]] + P2[dst[e]]
// 256 threads = 8 warps, each warp computes a 16(M)x128(N) tile, K=64,
// via mma.sync m16n8k16 bf16 with hi/lo split (3 products).
__global__ void __launch_bounds__(256, 1) k_edge_mma(const float* __restrict__ nbr,
                                                     const int* __restrict__ esrc,
                                                     const int* __restrict__ edst, int E) {
    __shared__ uint2 s_wh[2048];
    __shared__ uint2 s_wl[2048];
    const int tid = threadIdx.x, lane = tid & 31, w = tid >> 5;
    const int g = lane >> 2, tig = lane & 3;

    for (int i = tid; i < 2048; i += 256) {
        s_wh[i] = g_wfh[i];
        s_wl[i] = g_wfl[i];
    }

    const int e0 = blockIdx.x * 128 + w * 16 + g;
    const int e1 = e0 + 8;
    const bool v0 = e0 < E, v1 = e1 < E;

    // ---- load A fragments straight from gmem, split into bf16 hi/lo ----
    uint32_t ah[16], al[16];   // [kk][4]
    {
        const float* r0 = nbr + (size_t)e0 * 64;
        const float* r1 = nbr + (size_t)e1 * 64;
#pragma unroll
        for (int kk = 0; kk < 4; kk++) {
            int cA = 16 * kk + 2 * tig;
            float2 x0a = v0 ? *(const float2*)(r0 + cA)     : make_float2(0.f, 0.f);
            float2 x0b = v0 ? *(const float2*)(r0 + cA + 8) : make_float2(0.f, 0.f);
            float2 x1a = v1 ? *(const float2*)(r1 + cA)     : make_float2(0.f, 0.f);
            float2 x1b = v1 ? *(const float2*)(r1 + cA + 8) : make_float2(0.f, 0.f);
            uint32_t h;
            h = packbf(x0a.x, x0a.y); ah[kk*4+0] = h;
            { __nv_bfloat162 t = *(__nv_bfloat162*)&h;
              al[kk*4+0] = packbf(x0a.x - __bfloat162float(t.x), x0a.y - __bfloat162float(t.y)); }
            h = packbf(x1a.x, x1a.y); ah[kk*4+1] = h;
            { __nv_bfloat162 t = *(__nv_bfloat162*)&h;
              al[kk*4+1] = packbf(x1a.x - __bfloat162float(t.x), x1a.y - __bfloat162float(t.y)); }
            h = packbf(x0b.x, x0b.y); ah[kk*4+2] = h;
            { __nv_bfloat162 t = *(__nv_bfloat162*)&h;
              al[kk*4+2] = packbf(x0b.x - __bfloat162float(t.x), x0b.y - __bfloat162float(t.y)); }
            h = packbf(x1b.x, x1b.y); ah[kk*4+3] = h;
            { __nv_bfloat162 t = *(__nv_bfloat162*)&h;
              al[kk*4+3] = packbf(x1b.x - __bfloat162float(t.x), x1b.y - __bfloat162float(t.y)); }
        }
    }
    __syncthreads();

    // ---- mma mainloop ----
    float acc[64];
#pragma unroll
    for (int i = 0; i < 64; i++) acc[i] = 0.0f;

#pragma unroll
    for (int nt = 0; nt < 16; nt++) {
        float* c = acc + nt * 4;
#pragma unroll
        for (int kk = 0; kk < 4; kk++) {
            uint2 bh = s_wh[(kk * 16 + nt) * 32 + lane];
            uint2 bl = s_wl[(kk * 16 + nt) * 32 + lane];
            MMA_BF16(c, ah + kk * 4, bh.x, bh.y);   // Ah * Bh
            MMA_BF16(c, al + kk * 4, bh.x, bh.y);   // Al * Bh
            MMA_BF16(c, ah + kk * 4, bl.x, bl.y);   // Ah * Bl
        }
    }

    // ---- epilogue: gather P, write z, red stats ----
    int s0 = 0, d0 = 0, s1 = 0, d1 = 0;
    if (v0) { s0 = esrc[e0]; d0 = edst[e0]; }
    if (v1) { s1 = esrc[e1]; d1 = edst[e1]; }
    const int rep = blockIdx.x & (NREP - 1);
    float* gsum = g_sumf[rep];
    float* gsq  = g_sqf[rep];

#pragma unroll
    for (int nt = 0; nt < 16; nt++) {
        int col = nt * 8 + 2 * tig;
        float2 o0 = make_float2(0.f, 0.f), o1 = make_float2(0.f, 0.f);
        if (v0) {
            float2 p = *(const float2*)&g_P[(size_t)s0 * 256 + col];
            float2 q = *(const float2*)&g_P[(size_t)d0 * 256 + 128 + col];
            o0.x = acc[nt*4+0] + p.x + q.x;
            o0.y = acc[nt*4+1] + p.y + q.y;
            *(float2*)&g_z[(size_t)e0 * 128 + col] = o0;
        }
        if (v1) {
            float2 p = *(const float2*)&g_P[(size_t)s1 * 256 + col];
            float2 q = *(const float2*)&g_P[(size_t)d1 * 256 + 128 + col];
            o1.x = acc[nt*4+2] + p.x + q.x;
            o1.y = acc[nt*4+3] + p.y + q.y;
            *(float2*)&g_z[(size_t)e1 * 128 + col] = o1;
        }
        float sx = o0.x + o1.x, sy = o0.y + o1.y;
        float qx = o0.x * o0.x + o1.x * o1.x, qy = o0.y * o0.y + o1.y * o1.y;
        asm volatile("red.global.add.v2.f32 [%0], {%1, %2};" :: "l"(gsum + col), "f"(sx), "f"(sy) : "memory");
        asm volatile("red.global.add.v2.f32 [%0], {%1, %2};" :: "l"(gsq  + col), "f"(qx), "f"(qy) : "memory");
    }
}

// ---------------------------------------------------------------- K3: BN1 finalize
__global__ void k_bn1(const float* __restrict__ g1, const float* __restrict__ b1, int E) {
    int j = threadIdx.x;  // 128
    double s = 0.0, q = 0.0;
    for (int r = 0; r < NREP; r++) { s += (double)g_sumf[r][j]; q += (double)g_sqf[r][j]; }
    double mean = s / (double)E;
    double var  = q / (double)E - mean * mean;
    float istd = (float)rsqrt(var + 1e-5);
    float sc = g1[j] * istd;
    g_scale1[j] = sc;
    g_shift1[j] = b1[j] - (float)mean * sc;
}

// ---------------------------------------------------------------- K4: BN1 + gated message + scatter-add
__global__ void k_msg(const int* __restrict__ edst, int E) {
    int idx = blockIdx.x * blockDim.x + threadIdx.x;
    int gw = idx >> 5;
    int lane = threadIdx.x & 31;
    if (gw >= E) return;
    const float2* zr = (const float2*)(g_z + (size_t)gw * 128);
    float2 f = zr[lane];       // filter cols 2l, 2l+1
    float2 c = zr[32 + lane];  // core   cols 64+2l, 64+2l+1
    float2 sf = ((const float2*)g_scale1)[lane];
    float2 hf = ((const float2*)g_shift1)[lane];
    float2 sc = ((const float2*)g_scale1)[32 + lane];
    float2 hc = ((const float2*)g_shift1)[32 + lane];
    float m0 = sigmoidf(f.x * sf.x + hf.x) * softplusf(c.x * sc.x + hc.x);
    float m1 = sigmoidf(f.y * sf.y + hf.y) * softplusf(c.y * sc.y + hc.y);
    int d = edst[gw];
    float* p = &g_upd[(size_t)d * 64 + 2 * lane];
    asm volatile("red.global.add.v2.f32 [%0], {%1, %2};" :: "l"(p), "f"(m0), "f"(m1) : "memory");
}

// ---------------------------------------------------------------- K5: BN2 stats
__global__ void k_stats2(int N) {
    __shared__ double ssum[64], ssq[64];
    int tid = threadIdx.x;  // 256
    if (tid < 64) { ssum[tid] = 0.0; ssq[tid] = 0.0; }
    __syncthreads();
    int col = tid & 63;
    int r = blockIdx.x * 4 + (tid >> 6);
    float s = 0.0f, q = 0.0f;
    for (; r < N; r += gridDim.x * 4) {
        float v = g_upd[(size_t)r * 64 + col];
        s += v; q += v * v;
    }
    atomicAdd(&ssum[col], (double)s);
    atomicAdd(&ssq[col], (double)q);
    __syncthreads();
    if (tid < 64) {
        atomicAdd(&g_s2[tid], ssum[tid]);
        atomicAdd(&g_s2[64 + tid], ssq[tid]);
    }
}

// ---------------------------------------------------------------- K6: BN2 finalize
__global__ void k_bn2(const float* __restrict__ g2, const float* __restrict__ b2, int N) {
    int j = threadIdx.x;  // 64
    double mean = g_s2[j] / (double)N;
    double var  = g_s2[64 + j] / (double)N - mean * mean;
    float istd = (float)rsqrt(var + 1e-5);
    float sc = g2[j] * istd;
    g_scale2[j] = sc;
    g_shift2[j] = b2[j] - (float)mean * sc;
}

// ---------------------------------------------------------------- K7: output
__global__ void k_out(const float* __restrict__ atom, float* __restrict__ out, int N) {
    int i = blockIdx.x * blockDim.x + threadIdx.x;
    int total = N * 64;
    if (i >= total) return;
    int col = i & 63;
    float u = g_upd[i] * g_scale2[col] + g_shift2[col];
    out[i] = softplusf(atom[i] + u);
}

// ----------------------------------------------------------------
extern "C" void kernel_launch(void* const* d_in, const int* in_sizes, int n_in,
                              void* d_out, int out_size) {
    const float* atom = (const float*)d_in[0];
    const float* nbr  = (const float*)d_in[1];
    const int*   esrc = (const int*)d_in[2];
    const int*   edst = (const int*)d_in[3];
    const float* W    = (const float*)d_in[4];
    const float* b    = (const float*)d_in[5];
    const float* bn1g = (const float*)d_in[6];
    const float* bn1b = (const float*)d_in[7];
    const float* bn2g = (const float*)d_in[8];
    const float* bn2b = (const float*)d_in[9];
    float* out = (float*)d_out;

    int N = in_sizes[0] / 64;
    int E = in_sizes[2];

    k_zero<<<2048, 256>>>(N);
    k_prepW<<<8, 256>>>(W);
    dim3 gP(2, (N + 127) / 128);
    k_precompute<<<gP, 256>>>(atom, W, b, N);
    k_edge_mma<<<(E + 127) / 128, 256>>>(nbr, esrc, edst, E);
    k_bn1<<<1, 128>>>(bn1g, bn1b, E);
    {
        long long threads = (long long)E * 32;
        int grid = (int)((threads + 255) / 256);
        k_msg<<<grid, 256>>>(edst, E);
    }
    k_stats2<<<128, 256>>>(N);
    k_bn2<<<1, 64>>>(bn2g, bn2b, N);
    k_out<<<(N * 64 + 255) / 256, 256>>>(atom, out, N);
}